// round 17
// baseline (speedup 1.0000x reference)
#include <cuda_runtime.h>
#include <cuda_bf16.h>

#define BATCH 16384
#define FEAT 512
#define NCLS 100000
#define ALPHA 0.5f
#define LAMDA 0.003f

#define FUSED_BLOCKS (BATCH / 2)                       // 8192 (2 samples/block)
#define COPY_CHUNKS  (NCLS * (FEAT / 4) / 4)           // 3,200,000 64B chunks
#define COPY_BLOCKS  (COPY_CHUNKS / 256)               // 12500 (exact)
#define TOTAL_BLOCKS (FUSED_BLOCKS + COPY_BLOCKS)      // 20692

// Scratch (allocation-free __device__ globals, zero-initialized at load).
// INVARIANT: g_counts_f, g_counts_c, g_head are all-zero at kernel_launch
// entry. They are re-zeroed in-place by mega_kernel itself (fused blocks own
// g_counts_f[t]; each copy warp owns its row's g_counts_c/g_head), so the
// invariant holds for the correctness run, capture, and every replay.
// g_next needs no reset: every entry reachable from a head written this call
// was itself written this call.
__device__ int g_counts_f[NCLS];    // read+zeroed by fused half
__device__ int g_counts_c[NCLS];    // read+zeroed by copy half
__device__ int g_head[NCLS];        // per-class list head, sample_idx+1 (0=end)
__device__ int g_next[BATCH];       // linked-list next, sample_idx+1 (0=end)

__global__ void count_kernel(const int* __restrict__ targets) {
    int i = blockIdx.x * blockDim.x + threadIdx.x;
    if (i < BATCH) {
        int t = targets[i];
        atomicAdd(&g_counts_f[t], 1);
        atomicAdd(&g_counts_c[t], 1);
        g_next[i] = atomicExch(&g_head[t], i + 1);
    }
}

// Single worker grid, fused and copy blocks INTERLEAVED at fine grain
// (Bresenham mapping: exactly FUSED_BLOCKS bids are fused, evenly spread),
// so every scheduling wave mixes latency-bound gather work with pure
// streaming copy that keeps DRAM saturated.
//
// Fused block (2 samples, 128 threads each): loss + tw for the sample;
//   cnt==1 classes get their center row rewritten directly from registers.
//   Zeroes g_counts_f[t] after a block sync (benign cross-block race on
//   duplicate classes: 0 and >=2 both mean "not mine").
// Copy block (8 rows, 1 warp per 2KB row, 64B per lane): cnt==1 rows are
//   skipped (fused owns them); cnt==0 rows stream-copied; cnt>1 rows (~1.2%)
//   walk the class's sample list (warp-uniform, ~2 iters) and write
//   c - s*sum(x) directly — no atomics, no post-pass. Each warp zeroes its
//   row's g_counts_c/g_head after reading them.
__global__ __launch_bounds__(256) void mega_kernel(
    const float4* __restrict__ inputs,
    const float4* __restrict__ centers,
    const float*  __restrict__ wpc,
    const int*    __restrict__ targets,
    float4* __restrict__ loss_out,
    float4* __restrict__ tw_out,
    float4* __restrict__ new_centers) {

    const int bid = blockIdx.x;
    const long long fb = (long long)bid * FUSED_BLOCKS;
    const int f_before = (int)(fb / TOTAL_BLOCKS);
    const int f_after  = (int)((fb + FUSED_BLOCKS) / TOTAL_BLOCKS);

    if (f_after > f_before) {
        // ---- fused block #f_before: 2 samples, 128 threads each ----
        const int group = threadIdx.x >> 7;         // 0..1
        const int d4    = threadIdx.x & 127;        // 0..127
        const int b = f_before * 2 + group;

        const int t   = __ldg(&targets[b]);
        const int cnt = g_counts_f[t];
        const float w = LAMDA * __ldg(&wpc[t]);

        const size_t ib = (size_t)b * (FEAT / 4) + d4;
        const size_t ic = (size_t)t * (FEAT / 4) + d4;
        const float4 x = inputs[ib];
        const float4 c = centers[ic];

        // All threads have read cnt; now self-zero the scratch entry.
        __syncthreads();
        if (d4 == 0) g_counts_f[t] = 0;

        float4 l;
        float dx;
        dx = x.x - c.x; l.x = 0.5f * dx * dx;
        dx = x.y - c.y; l.y = 0.5f * dx * dx;
        dx = x.z - c.z; l.z = 0.5f * dx * dx;
        dx = x.w - c.w; l.w = 0.5f * dx * dx;

        loss_out[ib] = l;
        tw_out[ib]   = make_float4(w, w, w, w);

        if (cnt == 1) {
            const float s = ALPHA / 2.0f;           // cnt==1 -> ALPHA/(1+1)
            new_centers[ic] = make_float4(c.x - s * x.x, c.y - s * x.y,
                                          c.z - s * x.z, c.w - s * x.w);
        }
        // cnt != 1: row finalized by its copy warp via the class list.
    } else {
        // ---- copy block #(bid - f_before): warp == one 2KB row ----
        const int cbid = bid - f_before;
        const int tchunk = cbid * 256 + threadIdx.x;
        const size_t i = (size_t)tchunk * 4;        // float4 index
        const int row = (int)(i >> 7);              // 128 float4 per row
        // COPY_BLOCKS*256*4 == NCLS*128 exactly: row is always in range.

        const int cnt  = g_counts_c[row];
        const int head = g_head[row];
        __syncwarp();                               // all lanes read first
        if ((threadIdx.x & 31) == 0) {              // sole-owner self-zero
            g_counts_c[row] = 0;
            g_head[row] = 0;
        }
        if (cnt == 1) return;                       // fused half owns it

        float4 c0 = __ldcs(&centers[i + 0]);
        float4 c1 = __ldcs(&centers[i + 1]);
        float4 c2 = __ldcs(&centers[i + 2]);
        float4 c3 = __ldcs(&centers[i + 3]);

        if (cnt > 1) {
            // Warp-uniform list walk: sum inputs of this class's samples.
            const int col = (int)(i & 127);         // float4 offset in row
            float4 a0 = make_float4(0.f, 0.f, 0.f, 0.f);
            float4 a1 = a0, a2 = a0, a3 = a0;
            int h = head;
            while (h) {
                const int b = h - 1;
                const float4* xr = inputs + (size_t)b * (FEAT / 4) + col;
                float4 x0 = __ldcs(&xr[0]);
                float4 x1 = __ldcs(&xr[1]);
                float4 x2 = __ldcs(&xr[2]);
                float4 x3 = __ldcs(&xr[3]);
                a0.x += x0.x; a0.y += x0.y; a0.z += x0.z; a0.w += x0.w;
                a1.x += x1.x; a1.y += x1.y; a1.z += x1.z; a1.w += x1.w;
                a2.x += x2.x; a2.y += x2.y; a2.z += x2.z; a2.w += x2.w;
                a3.x += x3.x; a3.y += x3.y; a3.z += x3.z; a3.w += x3.w;
                h = g_next[b];
            }
            const float s = ALPHA / (1.0f + (float)cnt);
            c0.x -= s * a0.x; c0.y -= s * a0.y; c0.z -= s * a0.z; c0.w -= s * a0.w;
            c1.x -= s * a1.x; c1.y -= s * a1.y; c1.z -= s * a1.z; c1.w -= s * a1.w;
            c2.x -= s * a2.x; c2.y -= s * a2.y; c2.z -= s * a2.z; c2.w -= s * a2.w;
            c3.x -= s * a3.x; c3.y -= s * a3.y; c3.z -= s * a3.z; c3.w -= s * a3.w;
        }
        __stcs(&new_centers[i + 0], c0);
        __stcs(&new_centers[i + 1], c1);
        __stcs(&new_centers[i + 2], c2);
        __stcs(&new_centers[i + 3], c3);
    }
}

extern "C" void kernel_launch(void* const* d_in, const int* in_sizes, int n_in,
                              void* d_out, int out_size) {
    const float* inputs  = (const float*)d_in[0];   // [BATCH, FEAT]
    const float* centers = (const float*)d_in[1];   // [NCLS, FEAT]
    const float* wpc     = (const float*)d_in[2];   // [NCLS]
    const int*   targets = (const int*)d_in[3];     // [BATCH]

    float* out  = (float*)d_out;
    float* loss = out;                                  // [BATCH, FEAT]
    float* tw   = out + (size_t)BATCH * FEAT;           // [BATCH, FEAT]
    float* newc = out + (size_t)2 * BATCH * FEAT;       // [NCLS, FEAT]

    count_kernel<<<(BATCH + 255) / 256, 256>>>(targets);

    mega_kernel<<<TOTAL_BLOCKS, 256>>>(
        (const float4*)inputs, (const float4*)centers, wpc, targets,
        (float4*)loss, (float4*)tw, (float4*)newc);
}